// round 6
// baseline (speedup 1.0000x reference)
#include <cuda_runtime.h>
#include <cuda_bf16.h>
#include <cstdint>

#define BATCH 4
#define NCLS 19
#define IMH 512
#define IMW 1024
#define HW (IMH * IMW)           // 524288 = 2^19
#define NPIX (BATCH * HW)
#define KTOP 256
#define EPSF 1e-6f

// ---------------- scratch (static device arrays; no allocation) ----------------
__device__ float         g_entropy[NPIX];      // normalized per-pixel entropy
__device__ unsigned char g_label[NPIX];        // per-pixel argmax class
__device__ float         g_score[NPIX];        // per-pixel region score
__device__ unsigned int  g_hist0[BATCH * 2048];
__device__ unsigned int  g_hist1[BATCH * 2048];
__device__ unsigned int  g_hist2[BATCH * 2048];
__device__ unsigned int  g_sel_k[BATCH];       // remaining k at current radix level
__device__ unsigned int  g_sel_key[BATCH];     // accumulated bit prefix; after L2 = v* bits
__device__ float         g_sum[BATCH];
__device__ unsigned int  g_cnt[BATCH];

// ---------------- kernel 0: zero/init scratch ----------------
__global__ void k_init() {
    int idx = blockIdx.x * blockDim.x + threadIdx.x;
    int tot = BATCH * 2048;
    if (idx < tot) { g_hist0[idx] = 0; g_hist1[idx] = 0; g_hist2[idx] = 0; }
    if (idx < BATCH) {
        g_sum[idx] = 0.0f; g_cnt[idx] = 0;
        g_sel_k[idx] = KTOP; g_sel_key[idx] = 0;
    }
}

// ---------------- kernel 1: per-pixel entropy + argmax ----------------
__global__ void k_pixel(const float* __restrict__ logit) {
    int pix = blockIdx.x * blockDim.x + threadIdx.x;
    if (pix >= NPIX) return;
    int b  = pix >> 19;          // / HW
    int hw = pix & (HW - 1);
    const float* base = logit + (size_t)b * NCLS * HW + hw;

    const float invLogC = 1.0f / logf((float)NCLS);
    float ent = 0.0f;
    float best = -1.0f;
    int   bestc = 0;
#pragma unroll
    for (int c = 0; c < NCLS; c++) {
        float p = base[(size_t)c * HW];
        ent += -p * logf(p + EPSF);
        if (p > best) { best = p; bestc = c; }
    }
    g_entropy[pix] = ent * invLogC;
    g_label[pix]   = (unsigned char)bestc;
}

// ---------------- kernel 2: 3x3 region score + level-0 histogram ----------------
#define TBX 32
#define TBY 8
__global__ void k_region(void) {
    __shared__ float         s_ent[TBY + 2][TBX + 2];
    __shared__ unsigned char s_lab[TBY + 2][TBX + 2];
    __shared__ unsigned int  s_hist[2048];

    int b  = blockIdx.z;
    int bx = blockIdx.x * TBX;
    int by = blockIdx.y * TBY;
    int tx = threadIdx.x, ty = threadIdx.y;
    int tid = ty * TBX + tx;

    for (int i = tid; i < 2048; i += TBX * TBY) s_hist[i] = 0;

    // cooperative halo load: (TBY+2)x(TBX+2) = 340 elements
    const int TILE = (TBY + 2) * (TBX + 2);
    for (int i = tid; i < TILE; i += TBX * TBY) {
        int ly = i / (TBX + 2), lx = i % (TBX + 2);
        int gy = by + ly - 1, gx = bx + lx - 1;
        bool ok = (gy >= 0 && gy < IMH && gx >= 0 && gx < IMW);
        int gidx = b * HW + gy * IMW + gx;
        s_ent[ly][lx] = ok ? g_entropy[gidx] : 0.0f;
        s_lab[ly][lx] = ok ? g_label[gidx] : (unsigned char)255;
    }
    __syncthreads();

    // gather 3x3 taps
    float entsum = 0.0f;
    int   lab[9];
    int   n = 0;
#pragma unroll
    for (int dy = 0; dy < 3; dy++)
#pragma unroll
        for (int dx = 0; dx < 3; dx++) {
            entsum += s_ent[ty + dy][tx + dx];
            int L = s_lab[ty + dy][tx + dx];
            lab[dy * 3 + dx] = L;
            n += (L != 255);
        }

    float ru = entsum * (1.0f / 9.0f);

    const float invLogC = 1.0f / logf((float)NCLS);
    float invn = 1.0f / (float)n;
    float imp = 0.0f;
#pragma unroll
    for (int i = 0; i < 9; i++) {
        int Li = lab[i];
        if (Li == 255) continue;
        bool first = true;
#pragma unroll
        for (int j = 0; j < 9; j++)
            if (j < i && lab[j] == Li) first = false;
        if (first) {
            int c = 0;
#pragma unroll
            for (int j = 0; j < 9; j++) c += (lab[j] == Li);
            float p = (float)c * invn;
            imp -= p * logf(p + EPSF);
        }
    }
    imp *= invLogC;

    float sc = ru * imp;
    int y = by + ty, x = bx + tx;
    g_score[b * HW + y * IMW + x] = sc;

    unsigned int bits = __float_as_uint(sc);   // sc >= 0 -> uint order == float order
    atomicAdd(&s_hist[bits >> 21], 1u);
    __syncthreads();
    for (int i = tid; i < 2048; i += TBX * TBY) {
        unsigned int v = s_hist[i];
        if (v) atomicAdd(&g_hist0[b * 2048 + i], v);
    }
}

// ---------------- radix select level: find bin where top-cumulative crosses k ----------------
__global__ void k_select(const unsigned int* __restrict__ hist, int nbins, int lvbits) {
    int b = blockIdx.x;
    const unsigned int* h = hist + b * 2048;
    __shared__ unsigned int spair[1024];
    __shared__ unsigned int sv0[1024], sv1[1024];
    int t = threadIdx.x;

    // reversed order: position r corresponds to bin (nbins-1-r)
    unsigned int v0 = (2 * t     < nbins) ? h[nbins - 1 - 2 * t]       : 0;
    unsigned int v1 = (2 * t + 1 < nbins) ? h[nbins - 1 - (2 * t + 1)] : 0;
    sv0[t] = v0; sv1[t] = v1;
    spair[t] = v0 + v1;
    __syncthreads();
    // Hillis-Steele inclusive scan over 1024 pair-sums
    for (int off = 1; off < 1024; off <<= 1) {
        unsigned int x = spair[t];
        unsigned int y = (t >= off) ? spair[t - off] : 0;
        __syncthreads();
        spair[t] = x + y;
        __syncthreads();
    }
    unsigned int excl = (t > 0) ? spair[t - 1] : 0;
    unsigned int k = g_sel_k[b];
    unsigned int key = g_sel_key[b];
    __syncthreads();

    // element 2t (bin nbins-1-2t): excl prefix = excl
    if (excl < k && k <= excl + v0) {
        unsigned int bin = (unsigned int)(nbins - 1 - 2 * t);
        g_sel_k[b]   = k - excl;
        g_sel_key[b] = (key << lvbits) | bin;
    }
    unsigned int excl2 = excl + v0;
    if (excl2 < k && k <= excl2 + v1) {
        unsigned int bin = (unsigned int)(nbins - 1 - (2 * t + 1));
        g_sel_k[b]   = k - excl2;
        g_sel_key[b] = (key << lvbits) | bin;
    }
}

// ---------------- refine histogram pass (levels 1 and 2) ----------------
// level 1: match (bits>>21)==key, bin=(bits>>10)&0x7FF -> g_hist1
// level 2: match (bits>>10)==key, bin= bits & 0x3FF     -> g_hist2
__global__ void k_hist_refine(unsigned int* __restrict__ hist,
                              int matchShift, int binShift, unsigned int binMask) {
    int b = blockIdx.y;
    unsigned int key = g_sel_key[b];
    const float* sc = g_score + b * HW;
    int stride = gridDim.x * blockDim.x;
    for (int i = blockIdx.x * blockDim.x + threadIdx.x; i < HW; i += stride) {
        unsigned int bits = __float_as_uint(sc[i]);
        if ((bits >> matchShift) == key)
            atomicAdd(&hist[b * 2048 + ((bits >> binShift) & binMask)], 1u);
    }
}

// ---------------- final: sum of values strictly greater than v* ----------------
__global__ void k_final_sum(void) {
    int b = blockIdx.y;
    unsigned int vstar = g_sel_key[b];   // full 32-bit pattern after level 2
    const float* sc = g_score + b * HW;
    float lsum = 0.0f; unsigned int lcnt = 0;
    int stride = gridDim.x * blockDim.x;
    for (int i = blockIdx.x * blockDim.x + threadIdx.x; i < HW; i += stride) {
        unsigned int bits = __float_as_uint(sc[i]);
        if (bits > vstar) { lsum += sc[i]; lcnt++; }
    }
    // warp reduce
    for (int off = 16; off > 0; off >>= 1) {
        lsum += __shfl_down_sync(0xFFFFFFFFu, lsum, off);
        lcnt += __shfl_down_sync(0xFFFFFFFFu, lcnt, off);
    }
    __shared__ float swsum[8];
    __shared__ unsigned int swcnt[8];
    int wid = threadIdx.x >> 5, lid = threadIdx.x & 31;
    if (lid == 0) { swsum[wid] = lsum; swcnt[wid] = lcnt; }
    __syncthreads();
    if (threadIdx.x == 0) {
        float bs = 0.0f; unsigned int bc = 0;
        int nw = blockDim.x >> 5;
        for (int w = 0; w < nw; w++) { bs += swsum[w]; bc += swcnt[w]; }
        if (bc || bs != 0.0f) { atomicAdd(&g_sum[b], bs); atomicAdd(&g_cnt[b], bc); }
    }
}

__global__ void k_finalize(float* __restrict__ out) {
    int b = threadIdx.x;
    if (b < BATCH) {
        float vstar = __uint_as_float(g_sel_key[b]);
        out[b] = g_sum[b] + (float)(KTOP - (int)g_cnt[b]) * vstar;
    }
}

// ---------------- launch ----------------
extern "C" void kernel_launch(void* const* d_in, const int* in_sizes, int n_in,
                              void* d_out, int out_size) {
    const float* logit = (const float*)d_in[0];
    float* out = (float*)d_out;

    unsigned int *h0, *h1, *h2;
    cudaGetSymbolAddress((void**)&h0, g_hist0);
    cudaGetSymbolAddress((void**)&h1, g_hist1);
    cudaGetSymbolAddress((void**)&h2, g_hist2);

    k_init<<<(BATCH * 2048 + 255) / 256, 256>>>();
    k_pixel<<<NPIX / 256, 256>>>(logit);
    k_region<<<dim3(IMW / TBX, IMH / TBY, BATCH), dim3(TBX, TBY)>>>();
    k_select<<<BATCH, 1024>>>(h0, 2048, 11);
    k_hist_refine<<<dim3(256, BATCH), 256>>>(h1, 21, 10, 0x7FFu);
    k_select<<<BATCH, 1024>>>(h1, 2048, 11);
    k_hist_refine<<<dim3(256, BATCH), 256>>>(h2, 10, 0, 0x3FFu);
    k_select<<<BATCH, 1024>>>(h2, 1024, 10);
    k_final_sum<<<dim3(256, BATCH), 256>>>();
    k_finalize<<<1, BATCH>>>(out);
}

// round 9
// speedup vs baseline: 1.7175x; 1.7175x over previous
#include <cuda_runtime.h>
#include <cuda_bf16.h>
#include <cstdint>

#define BATCH 4
#define NCLS 19
#define IMH 512
#define IMW 1024
#define HW (IMH * IMW)           // 524288 = 2^19
#define NPIX (BATCH * HW)
#define KTOP 256
#define EPSF 1e-6f

// ---------------- scratch (static device arrays; no allocation) ----------------
__device__ float         g_entropy[NPIX];
__device__ unsigned char g_label[NPIX];
__device__ float         g_score[NPIX];
__device__ unsigned int  g_hist0[BATCH * 2048];
__device__ unsigned int  g_hist1[BATCH * 2048];
__device__ unsigned int  g_hist2[BATCH * 1024];
__device__ unsigned int  g_sel_k[BATCH];
__device__ unsigned int  g_sel_key[BATCH];
__device__ float         g_sum[BATCH];
__device__ unsigned int  g_cnt[BATCH];
__device__ unsigned int  g_ctr[4 * BATCH];   // last-block counters per phase per batch

// ---------------- shared select routine (run by ONE block, 256 threads) --------
// Finds the bin (scanning from highest bin down) where the cumulative count
// crosses the remaining k. Updates g_sel_k / g_sel_key. Uses __ldcg (L2) loads
// because the histogram was produced by global atomics from other SMs.
__device__ __forceinline__ void do_select(const unsigned int* __restrict__ h,
                                          int nbins, int lvbits, int b, int tid) {
    const int T = 256;
    int cs = nbins / T;                 // bins per thread (descending chunk)
    int base = nbins - 1 - tid * cs;
    unsigned int csum = 0;
    for (int i = 0; i < cs; i++) csum += __ldcg(&h[base - i]);

    // inclusive block scan of 256 chunk sums
    unsigned int v = csum;
    #pragma unroll
    for (int off = 1; off < 32; off <<= 1) {
        unsigned int y = __shfl_up_sync(0xFFFFFFFFu, v, off);
        if ((tid & 31) >= off) v += y;
    }
    __shared__ unsigned int s_wsum[8];
    if ((tid & 31) == 31) s_wsum[tid >> 5] = v;
    __syncthreads();
    if (tid < 8) {
        unsigned int w = s_wsum[tid];
        #pragma unroll
        for (int off = 1; off < 8; off <<= 1) {
            unsigned int y = __shfl_up_sync(0xFFu, w, off);
            if (tid >= off) w += y;
        }
        s_wsum[tid] = w;   // inclusive warp prefix
    }
    __syncthreads();
    unsigned int incl = v + ((tid >= 32) ? s_wsum[(tid >> 5) - 1] : 0u);
    unsigned int excl = incl - csum;

    unsigned int k = g_sel_k[b];
    if (excl < k && k <= incl) {
        unsigned int run = excl;
        for (int i = 0; i < cs; i++) {
            unsigned int hv = __ldcg(&h[base - i]);
            if (run < k && k <= run + hv) {
                g_sel_k[b]   = k - run;
                g_sel_key[b] = (g_sel_key[b] << lvbits) | (unsigned int)(base - i);
                break;
            }
            run += hv;
        }
    }
}

// ---------------- kernel 1: per-pixel entropy + argmax (float4, fused init) ----
__global__ void k_pixel(const float* __restrict__ logit) {
    // fused scratch init (block 0 only; no other block touches these buffers here)
    if (blockIdx.x == 0) {
        int t = threadIdx.x;
        for (int i = t; i < 2048 * BATCH; i += 256) { g_hist0[i] = 0; g_hist1[i] = 0; }
        for (int i = t; i < 1024 * BATCH; i += 256) g_hist2[i] = 0;
        if (t < BATCH) { g_sel_k[t] = KTOP; g_sel_key[t] = 0; g_sum[t] = 0.0f; g_cnt[t] = 0; }
        if (t < 4 * BATCH) g_ctr[t] = 0;
    }

    int idx = blockIdx.x * blockDim.x + threadIdx.x;   // one float4 (4 pixels)
    int p4 = idx * 4;
    int b  = p4 >> 19;
    int hw = p4 & (HW - 1);
    const float4* base = (const float4*)(logit + (size_t)b * NCLS * HW + hw);
    const int planeStride = HW / 4;

    float4 ent  = make_float4(0.f, 0.f, 0.f, 0.f);
    float4 best = make_float4(-1.f, -1.f, -1.f, -1.f);
    int bc0 = 0, bc1 = 0, bc2 = 0, bc3 = 0;
    #pragma unroll
    for (int c = 0; c < NCLS; c++) {
        float4 p = base[c * planeStride];
        ent.x -= p.x * __logf(p.x + EPSF);
        ent.y -= p.y * __logf(p.y + EPSF);
        ent.z -= p.z * __logf(p.z + EPSF);
        ent.w -= p.w * __logf(p.w + EPSF);
        if (p.x > best.x) { best.x = p.x; bc0 = c; }
        if (p.y > best.y) { best.y = p.y; bc1 = c; }
        if (p.z > best.z) { best.z = p.z; bc2 = c; }
        if (p.w > best.w) { best.w = p.w; bc3 = c; }
    }
    float invLogC = 1.0f / __logf((float)NCLS);
    ent.x *= invLogC; ent.y *= invLogC; ent.z *= invLogC; ent.w *= invLogC;
    ((float4*)g_entropy)[idx] = ent;
    ((uchar4*)g_label)[idx] = make_uchar4((unsigned char)bc0, (unsigned char)bc1,
                                          (unsigned char)bc2, (unsigned char)bc3);
}

// ---------------- kernel 2: 3x3 region score + hist0 + fused select0 ----------
#define TBX 32
#define TBY 8
__global__ void k_region(void) {
    __shared__ float         s_ent[TBY + 2][TBX + 2];
    __shared__ unsigned char s_lab[TBY + 2][TBX + 2];
    __shared__ unsigned int  s_hist[2048];
    __shared__ float         s_T[48];           // impurity table: [nIdx*16 + count]
    __shared__ int           s_last;

    int b  = blockIdx.z;
    int bx = blockIdx.x * TBX;
    int by = blockIdx.y * TBY;
    int tx = threadIdx.x, ty = threadIdx.y;
    int tid = ty * TBX + tx;

    for (int i = tid; i < 2048; i += 256) s_hist[i] = 0;

    // impurity lookup table: T[nIdx][c] = -(c/n)*log(c/n+eps)/logC, n in {4,6,9}
    if (tid < 48) {
        int nIdx = tid >> 4, c = tid & 15;
        float n = (nIdx == 0) ? 4.0f : (nIdx == 1) ? 6.0f : 9.0f;
        float val = 0.0f;
        if (c >= 1 && c <= 9) {
            float p = (float)c / n;
            val = -p * __logf(p + EPSF) * (1.0f / __logf((float)NCLS));
        }
        s_T[tid] = val;
    }

    // halo tile load
    const int TILE = (TBY + 2) * (TBX + 2);
    for (int i = tid; i < TILE; i += 256) {
        int ly = i / (TBX + 2), lx = i % (TBX + 2);
        int gy = by + ly - 1, gx = bx + lx - 1;
        bool ok = (gy >= 0 && gy < IMH && gx >= 0 && gx < IMW);
        int gidx = b * HW + gy * IMW + gx;
        s_ent[ly][lx] = ok ? g_entropy[gidx] : 0.0f;
        s_lab[ly][lx] = ok ? g_label[gidx] : (unsigned char)255;
    }
    __syncthreads();

    // 3x3 gather: entropy sum + nibble-packed class counts
    float entsum = 0.0f;
    unsigned long long accLo = 0ull;   // classes 0..15, 4-bit counters
    unsigned int accHi = 0u;           // classes 16..18
    int n = 0;
    #pragma unroll
    for (int dy = 0; dy < 3; dy++)
    #pragma unroll
        for (int dx = 0; dx < 3; dx++) {
            entsum += s_ent[ty + dy][tx + dx];
            int L = s_lab[ty + dy][tx + dx];
            if (L < 16)        { accLo += 1ull << (L * 4);        n++; }
            else if (L != 255) { accHi += 1u   << ((L - 16) * 4); n++; }
        }

    int nIdx = (n == 9) ? 2 : ((n == 6) ? 1 : 0);
    const float* T = s_T + nIdx * 16;
    float imp = 0.0f;
    #pragma unroll
    for (int c = 0; c < 16; c++) imp += T[(unsigned int)(accLo >> (c * 4)) & 15u];
    #pragma unroll
    for (int c = 0; c < 3; c++)  imp += T[(accHi >> (c * 4)) & 15u];

    float sc = entsum * (1.0f / 9.0f) * imp;
    g_score[b * HW + (by + ty) * IMW + (bx + tx)] = sc;

    unsigned int bits = __float_as_uint(sc);     // sc >= 0 => uint order == float order
    atomicAdd(&s_hist[bits >> 21], 1u);
    __syncthreads();
    for (int i = tid; i < 2048; i += 256) {
        unsigned int v = s_hist[i];
        if (v) atomicAdd(&g_hist0[b * 2048 + i], v);
    }

    // last-block-done -> select level 0 for this batch
    __threadfence();
    __syncthreads();
    if (tid == 0) {
        unsigned int done = atomicAdd(&g_ctr[0 * BATCH + b], 1u);
        s_last = (done == gridDim.x * gridDim.y - 1);
    }
    __syncthreads();
    if (s_last) do_select(g_hist0 + b * 2048, 2048, 11, b, tid);
}

// ---------------- refine histogram + fused select (levels 1 and 2) -------------
__global__ void k_refine(unsigned int* __restrict__ hist, int matchShift,
                         int binShift, unsigned int binMask, int nbins,
                         int lvbits, int phase) {
    __shared__ unsigned int s_hist[2048];
    __shared__ int s_last;
    int b = blockIdx.y;
    unsigned int key = g_sel_key[b];
    unsigned int* H = hist + b * nbins;

    for (int i = threadIdx.x; i < nbins; i += 256) s_hist[i] = 0;
    __syncthreads();

    const float4* sc = (const float4*)(g_score + b * HW);
    int nvec = HW / 4;
    int stride = gridDim.x * 256;
    for (int i = blockIdx.x * 256 + threadIdx.x; i < nvec; i += stride) {
        float4 v = sc[i];
        unsigned int bx;
        bx = __float_as_uint(v.x); if ((bx >> matchShift) == key) atomicAdd(&s_hist[(bx >> binShift) & binMask], 1u);
        bx = __float_as_uint(v.y); if ((bx >> matchShift) == key) atomicAdd(&s_hist[(bx >> binShift) & binMask], 1u);
        bx = __float_as_uint(v.z); if ((bx >> matchShift) == key) atomicAdd(&s_hist[(bx >> binShift) & binMask], 1u);
        bx = __float_as_uint(v.w); if ((bx >> matchShift) == key) atomicAdd(&s_hist[(bx >> binShift) & binMask], 1u);
    }
    __syncthreads();
    for (int i = threadIdx.x; i < nbins; i += 256) {
        unsigned int v = s_hist[i];
        if (v) atomicAdd(&H[i], v);
    }

    __threadfence();
    __syncthreads();
    if (threadIdx.x == 0) {
        unsigned int done = atomicAdd(&g_ctr[phase * BATCH + b], 1u);
        s_last = (done == gridDim.x - 1);
    }
    __syncthreads();
    if (s_last) do_select(H, nbins, lvbits, b, threadIdx.x);
}

// ---------------- final: sum of values > v*, fused finalize -------------------
__global__ void k_final(float* __restrict__ out) {
    __shared__ float        s_wsum[8];
    __shared__ unsigned int s_wcnt[8];
    __shared__ int s_last;
    int b = blockIdx.y;
    unsigned int vstar = g_sel_key[b];
    const float4* sc = (const float4*)(g_score + b * HW);
    int nvec = HW / 4;
    int stride = gridDim.x * 256;

    float lsum = 0.0f; unsigned int lcnt = 0;
    for (int i = blockIdx.x * 256 + threadIdx.x; i < nvec; i += stride) {
        float4 v = sc[i];
        if (__float_as_uint(v.x) > vstar) { lsum += v.x; lcnt++; }
        if (__float_as_uint(v.y) > vstar) { lsum += v.y; lcnt++; }
        if (__float_as_uint(v.z) > vstar) { lsum += v.z; lcnt++; }
        if (__float_as_uint(v.w) > vstar) { lsum += v.w; lcnt++; }
    }
    #pragma unroll
    for (int off = 16; off > 0; off >>= 1) {
        lsum += __shfl_down_sync(0xFFFFFFFFu, lsum, off);
        lcnt += __shfl_down_sync(0xFFFFFFFFu, lcnt, off);
    }
    int wid = threadIdx.x >> 5, lid = threadIdx.x & 31;
    if (lid == 0) { s_wsum[wid] = lsum; s_wcnt[wid] = lcnt; }
    __syncthreads();
    if (threadIdx.x == 0) {
        float bs = 0.0f; unsigned int bc = 0;
        #pragma unroll
        for (int w = 0; w < 8; w++) { bs += s_wsum[w]; bc += s_wcnt[w]; }
        atomicAdd(&g_sum[b], bs);
        atomicAdd(&g_cnt[b], bc);
    }
    __threadfence();
    __syncthreads();
    if (threadIdx.x == 0) {
        unsigned int done = atomicAdd(&g_ctr[3 * BATCH + b], 1u);
        s_last = (done == gridDim.x - 1);
    }
    __syncthreads();
    if (s_last && threadIdx.x == 0) {
        float s = __ldcg(&g_sum[b]);
        unsigned int c = __ldcg(&g_cnt[b]);
        out[b] = s + (float)(KTOP - (int)c) * __uint_as_float(vstar);
    }
}

// ---------------- launch ----------------
extern "C" void kernel_launch(void* const* d_in, const int* in_sizes, int n_in,
                              void* d_out, int out_size) {
    const float* logit = (const float*)d_in[0];
    float* out = (float*)d_out;

    unsigned int *h1, *h2;
    cudaGetSymbolAddress((void**)&h1, g_hist1);
    cudaGetSymbolAddress((void**)&h2, g_hist2);

    k_pixel<<<NPIX / 4 / 256, 256>>>(logit);
    k_region<<<dim3(IMW / TBX, IMH / TBY, BATCH), dim3(TBX, TBY)>>>();
    k_refine<<<dim3(64, BATCH), 256>>>(h1, 21, 10, 0x7FFu, 2048, 11, 1);
    k_refine<<<dim3(64, BATCH), 256>>>(h2, 10, 0, 0x3FFu, 1024, 10, 2);
    k_final<<<dim3(64, BATCH), 256>>>(out);
}